// round 3
// baseline (speedup 1.0000x reference)
#include <cuda_runtime.h>
#include <cuda_bf16.h>

#define NN 20000
#define EE 160000
#define HH 8
#define DKK 32
#define DD 256

// ---------------- scratch (static device globals; no allocation) ----------------
__device__ float g_k[NN * DD];
__device__ float g_q[NN * DD];
__device__ float g_v[NN * DD];
__device__ float g_mk[NN * DD];
__device__ float g_val[3][NN * DD];
__device__ float g_cval[3][NN * DD];
__device__ float g_attb[3][EE * HH];
__device__ float g_cattb[3][EE * HH];
__device__ float g_inva[3][NN * HH];
__device__ float g_invc[3][NN * HH];
__device__ int   g_cnt[3][NN];
__device__ int   g_cur[3][NN];
__device__ int   g_off[3][NN + 1];
__device__ int   g_ssrc[3][EE];
__device__ int   g_sdst[3][EE];

// ---------------- K1: fused QKV GEMM  out = x @ W + b --------------------------
// BM=64, BN=64, BK=16, 256 threads, 4x4 register tile.
__global__ __launch_bounds__(256) void k_gemm(
    const float* __restrict__ x,
    const float* __restrict__ Wk, const float* __restrict__ bk,
    const float* __restrict__ Wq, const float* __restrict__ bq,
    const float* __restrict__ Wv, const float* __restrict__ bv)
{
    __shared__ float As[16][64];
    __shared__ float Bs[16][64];

    int bm  = blockIdx.x * 64;
    int by  = blockIdx.y;                 // 0..11
    int mat = by >> 2;
    int bn  = (by & 3) * 64;

    const float* W    = (mat == 0) ? Wk : ((mat == 1) ? Wq : Wv);
    const float* bias = (mat == 0) ? bk : ((mat == 1) ? bq : bv);
    float*       out  = (mat == 0) ? g_k : ((mat == 1) ? g_q : g_v);

    int tid = threadIdx.x;
    int tx = tid & 15, ty = tid >> 4;

    int alm  = tid >> 2;          // row within A tile (0..63)
    int alk  = (tid & 3) * 4;     // k offset (0,4,8,12)
    int blk  = tid >> 4;          // k row for B (0..15)
    int bln  = (tid & 15) * 4;    // col offset (0..60)

    float acc[4][4];
#pragma unroll
    for (int i = 0; i < 4; i++)
#pragma unroll
        for (int j = 0; j < 4; j++) acc[i][j] = 0.f;

    for (int k0 = 0; k0 < 256; k0 += 16) {
        int m = bm + alm;
        float4 a4 = make_float4(0.f, 0.f, 0.f, 0.f);
        if (m < NN) a4 = *(const float4*)&x[m * 256 + k0 + alk];
        As[alk + 0][alm] = a4.x;
        As[alk + 1][alm] = a4.y;
        As[alk + 2][alm] = a4.z;
        As[alk + 3][alm] = a4.w;

        float4 b4 = *(const float4*)&W[(k0 + blk) * 256 + bn + bln];
        *(float4*)&Bs[blk][bln] = b4;
        __syncthreads();

#pragma unroll
        for (int kk = 0; kk < 16; kk++) {
            float4 av = *(const float4*)&As[kk][ty * 4];
            float4 bv4 = *(const float4*)&Bs[kk][tx * 4];
            float a[4] = {av.x, av.y, av.z, av.w};
            float b[4] = {bv4.x, bv4.y, bv4.z, bv4.w};
#pragma unroll
            for (int i = 0; i < 4; i++)
#pragma unroll
                for (int j = 0; j < 4; j++)
                    acc[i][j] = fmaf(a[i], b[j], acc[i][j]);
        }
        __syncthreads();
    }

    float4 bb = *(const float4*)&bias[bn + tx * 4];
    float bv4a[4] = {bb.x, bb.y, bb.z, bb.w};
#pragma unroll
    for (int i = 0; i < 4; i++) {
        int m = bm + ty * 4 + i;
        if (m < NN) {
            float4 o;
            o.x = acc[i][0] + bv4a[0];
            o.y = acc[i][1] + bv4a[1];
            o.z = acc[i][2] + bv4a[2];
            o.w = acc[i][3] + bv4a[3];
            *(float4*)&out[m * 256 + bn + tx * 4] = o;
        }
    }
}

// ---------------- K2: per-node 32x32 head transforms ---------------------------
// acc[f] += x[d] * M[d*32+f]  (M broadcast from smem; lane = node)
__device__ __forceinline__ void matvec32(const float* __restrict__ M,
                                         const float xv[32], float acc[32])
{
#pragma unroll
    for (int f = 0; f < 32; f++) acc[f] = 0.f;
#pragma unroll
    for (int d = 0; d < 32; d++) {
        float xd = xv[d];
#pragma unroll
        for (int f4 = 0; f4 < 8; f4++) {
            float4 m4 = *(const float4*)&M[d * 32 + f4 * 4];
            acc[f4 * 4 + 0] = fmaf(xd, m4.x, acc[f4 * 4 + 0]);
            acc[f4 * 4 + 1] = fmaf(xd, m4.y, acc[f4 * 4 + 1]);
            acc[f4 * 4 + 2] = fmaf(xd, m4.z, acc[f4 * 4 + 2]);
            acc[f4 * 4 + 3] = fmaf(xd, m4.w, acc[f4 * 4 + 3]);
        }
    }
}

__device__ __forceinline__ void store32(float* __restrict__ p, const float acc[32])
{
#pragma unroll
    for (int f4 = 0; f4 < 8; f4++) {
        float4 t = make_float4(acc[f4 * 4], acc[f4 * 4 + 1], acc[f4 * 4 + 2], acc[f4 * 4 + 3]);
        *(float4*)&p[f4 * 4] = t;
    }
}

__global__ __launch_bounds__(256) void k_transform(
    const float* __restrict__ msg,
    const float* __restrict__ msg_cau,
    const float* __restrict__ cau_filter,
    const float* __restrict__ time_emb,
    const int* __restrict__ cau_type)
{
    __shared__ float sMSG[3 * 1024];
    __shared__ float sMSGC[3 * 1024];
    __shared__ float sCF[3 * 1024];
    __shared__ float sTE[32];

    int h = blockIdx.y;
    int tid = threadIdx.x;
    for (int i = tid; i < 3 * 1024; i += 256) {
        int e = i >> 10, r = i & 1023;
        sMSG[i]  = msg[(e * 8 + h) * 1024 + r];
        sMSGC[i] = msg_cau[(e * 8 + h) * 1024 + r];
        sCF[i]   = cau_filter[(e * 8 + h) * 1024 + r];
    }
    if (tid < 32) sTE[tid] = time_emb[h * 32 + tid];
    __syncthreads();

    int node = blockIdx.x * 256 + tid;
    if (node >= NN) return;

    float xv[32], acc[32];
    const float* kr = &g_k[node * 256 + h * 32];
#pragma unroll
    for (int d4 = 0; d4 < 8; d4++) {
        float4 t = *(const float4*)&kr[d4 * 4];
        xv[d4 * 4 + 0] = t.x; xv[d4 * 4 + 1] = t.y;
        xv[d4 * 4 + 2] = t.z; xv[d4 * 4 + 3] = t.w;
    }
    int ct = cau_type[node];
    matvec32(&sCF[ct * 1024], xv, acc);
    store32(&g_mk[node * 256 + h * 32], acc);

    const float* vr = &g_v[node * 256 + h * 32];
#pragma unroll
    for (int d4 = 0; d4 < 8; d4++) {
        float4 t = *(const float4*)&vr[d4 * 4];
        xv[d4 * 4 + 0] = t.x; xv[d4 * 4 + 1] = t.y;
        xv[d4 * 4 + 2] = t.z; xv[d4 * 4 + 3] = t.w;
    }
    for (int e = 0; e < 3; e++) {
        matvec32(&sMSG[e * 1024], xv, acc);
        store32(&g_val[e][node * 256 + h * 32], acc);
    }
#pragma unroll
    for (int d = 0; d < 32; d++) xv[d] += sTE[d];
    for (int e = 0; e < 3; e++) {
        matvec32(&sMSGC[e * 1024], xv, acc);
        store32(&g_cval[e][node * 256 + h * 32], acc);
    }
}

// ---------------- K3: CSR build ------------------------------------------------
__global__ void k_zero()
{
    int i = blockIdx.x * 256 + threadIdx.x;
    if (i < 3 * NN) {
        ((int*)g_cnt)[i] = 0;
        ((int*)g_cur)[i] = 0;
    }
}

__global__ void k_count(const int* __restrict__ dst)
{
    int i = blockIdx.x * 256 + threadIdx.x;
    if (i < 3 * EE) {
        int e = i / EE;
        atomicAdd(&g_cnt[e][dst[i]], 1);
    }
}

__global__ __launch_bounds__(1024) void k_scan()
{
    __shared__ int s[1024];
    int t = threadIdx.x;
    for (int e = 0; e < 3; e++) {
        int carry = 0;
        if (t == 0) g_off[e][0] = 0;
        for (int base = 0; base < NN; base += 1024) {
            int v = (base + t < NN) ? g_cnt[e][base + t] : 0;
            s[t] = v;
            __syncthreads();
            for (int ofs = 1; ofs < 1024; ofs <<= 1) {
                int add = (t >= ofs) ? s[t - ofs] : 0;
                __syncthreads();
                s[t] += add;
                __syncthreads();
            }
            if (base + t < NN) g_off[e][base + t + 1] = carry + s[t];
            carry += s[1023];
            __syncthreads();
        }
    }
}

__global__ void k_scatter(const int* __restrict__ src, const int* __restrict__ dst)
{
    int i = blockIdx.x * 256 + threadIdx.x;
    if (i < 3 * EE) {
        int e = i / EE;
        int d = dst[i];
        int pos = g_off[e][d] + atomicAdd(&g_cur[e][d], 1);
        g_ssrc[e][pos] = src[i];
        g_sdst[e][pos] = d;
    }
}

// ---------------- K4: edge logits (warp per edge) ------------------------------
__global__ __launch_bounds__(256) void k_att(const float* __restrict__ pri,
                                             const float* __restrict__ pri_cau)
{
    int e = blockIdx.y;
    int w = blockIdx.x * 8 + (threadIdx.x >> 5);
    int l = threadIdx.x & 31;
    if (w >= EE) return;

    int s = g_ssrc[e][w];
    int d = g_sdst[e][w];

    // lane l covers head h=l/4, dk range [(l&3)*8, +8)
    const float* qp = &g_q[d * 256 + l * 8];
    const float* kp = &g_k[s * 256 + l * 8];
    const float* mp = &g_mk[s * 256 + l * 8];

    float4 q0 = *(const float4*)qp,        q1 = *(const float4*)(qp + 4);
    float4 k0 = *(const float4*)kp,        k1 = *(const float4*)(kp + 4);
    float4 m0 = *(const float4*)mp,        m1 = *(const float4*)(mp + 4);

    float pa = q0.x * k0.x + q0.y * k0.y + q0.z * k0.z + q0.w * k0.w
             + q1.x * k1.x + q1.y * k1.y + q1.z * k1.z + q1.w * k1.w;
    float pc = q0.x * m0.x + q0.y * m0.y + q0.z * m0.z + q0.w * m0.w
             + q1.x * m1.x + q1.y * m1.y + q1.z * m1.z + q1.w * m1.w;

    pa += __shfl_xor_sync(0xffffffffu, pa, 1);
    pa += __shfl_xor_sync(0xffffffffu, pa, 2);
    pc += __shfl_xor_sync(0xffffffffu, pc, 1);
    pc += __shfl_xor_sync(0xffffffffu, pc, 2);
    // lane 4h now holds full dot for head h (and its group)

    const float inv_sqrt = 0.17677669529663687f;  // 1/sqrt(32)
    float av = __shfl_sync(0xffffffffu, pa, (l & 7) * 4);
    float cv = __shfl_sync(0xffffffffu, pc, (l & 7) * 4);

    if (l < 8) {
        g_attb[e][w * 8 + l] = av * pri[e * 8 + l] * inv_sqrt;
    } else if (l < 16) {
        int h = l - 8;
        g_cattb[e][w * 8 + h] = cv * pri_cau[e * 8 + h] * inv_sqrt;
    }
}

// ---------------- K5: segment softmax (thread per node-head-etype) -------------
__global__ void k_soft()
{
    int i = blockIdx.x * 256 + threadIdx.x;
    if (i >= 3 * NN * HH) return;
    int e = i / (NN * HH);
    int rem = i - e * (NN * HH);
    int d = rem >> 3;
    int h = rem & 7;

    int st = g_off[e][d], en = g_off[e][d + 1];
    float m = -1e30f, m2 = -1e30f;
    for (int p = st; p < en; p++) {
        m  = fmaxf(m,  g_attb[e][p * 8 + h]);
        m2 = fmaxf(m2, g_cattb[e][p * 8 + h]);
    }
    float s = 0.f, s2 = 0.f;
    for (int p = st; p < en; p++) {
        float w  = __expf(g_attb[e][p * 8 + h] - m);
        float w2 = __expf(g_cattb[e][p * 8 + h] - m2);
        g_attb[e][p * 8 + h] = w;
        g_cattb[e][p * 8 + h] = w2;
        s += w; s2 += w2;
    }
    g_inva[e][d * 8 + h] = (en > st) ? 1.0f / s  : 0.0f;
    g_invc[e][d * 8 + h] = (en > st) ? 1.0f / s2 : 0.0f;
}

// ---------------- K6: aggregation (warp per dst node, loops etypes) ------------
__global__ __launch_bounds__(256) void k_agg(const float* __restrict__ comb_pri,
                                             float* __restrict__ out)
{
    int d = blockIdx.x * 8 + (threadIdx.x >> 5);
    int l = threadIdx.x & 31;
    if (d >= NN) return;

    float accO[8];
#pragma unroll
    for (int r = 0; r < 8; r++) accO[r] = 0.f;

    for (int e = 0; e < 3; e++) {
        int st = g_off[e][d], en = g_off[e][d + 1];
        float inv = 0.f;
        if (l < 8)        inv = g_inva[e][d * 8 + l];
        else if (l < 16)  inv = g_invc[e][d * 8 + (l - 8)];

        float aH[8], aC[8];
#pragma unroll
        for (int r = 0; r < 8; r++) { aH[r] = 0.f; aC[r] = 0.f; }

        for (int p = st; p < en; p++) {
            int s = g_ssrc[e][p];
            float wl = 0.f;
            if (l < 8)        wl = g_attb[e][p * 8 + l];
            else if (l < 16)  wl = g_cattb[e][p * 8 + (l - 8)];
            wl *= inv;

            const float* vp = &g_val[e][s * 256 + l];
            const float* cp = &g_cval[e][s * 256 + l];
#pragma unroll
            for (int r = 0; r < 8; r++) {
                float wr = __shfl_sync(0xffffffffu, wl, r);
                float cr = __shfl_sync(0xffffffffu, wl, r + 8);
                aH[r] = fmaf(wr, vp[r * 32], aH[r]);
                aC[r] = fmaf(cr, cp[r * 32], aC[r]);
            }
        }
#pragma unroll
        for (int r = 0; r < 8; r++) {
            float cpv = comb_pri[(e * 8 + r) * 32 + l];
            accO[r] += aH[r] + aC[r] * cpv;
        }
    }
#pragma unroll
    for (int r = 0; r < 8; r++)
        out[d * 256 + r * 32 + l] = fmaxf(accO[r] * (1.0f / 3.0f), 0.0f);
}

// ---------------- launch -------------------------------------------------------
extern "C" void kernel_launch(void* const* d_in, const int* in_sizes, int n_in,
                              void* d_out, int out_size)
{
    const float* x          = (const float*)d_in[0];
    const float* Wk         = (const float*)d_in[1];
    const float* bk         = (const float*)d_in[2];
    const float* Wq         = (const float*)d_in[3];
    const float* bq         = (const float*)d_in[4];
    const float* Wv         = (const float*)d_in[5];
    const float* bv         = (const float*)d_in[6];
    const float* pri        = (const float*)d_in[7];
    const float* msg        = (const float*)d_in[8];
    const float* pri_cau    = (const float*)d_in[9];
    const float* msg_cau    = (const float*)d_in[10];
    const float* comb_pri   = (const float*)d_in[11];
    const float* cau_filter = (const float*)d_in[12];
    const float* time_emb   = (const float*)d_in[13];
    const int*   cau_type   = (const int*)d_in[14];
    const int*   src        = (const int*)d_in[15];
    const int*   dst        = (const int*)d_in[16];
    float* out = (float*)d_out;

    k_gemm<<<dim3((NN + 63) / 64, 12), 256>>>(x, Wk, bk, Wq, bq, Wv, bv);
    k_transform<<<dim3((NN + 255) / 256, HH), 256>>>(msg, msg_cau, cau_filter,
                                                     time_emb, cau_type);
    k_zero<<<(3 * NN + 255) / 256, 256>>>();
    k_count<<<(3 * EE + 255) / 256, 256>>>(dst);
    k_scan<<<1, 1024>>>();
    k_scatter<<<(3 * EE + 255) / 256, 256>>>(src, dst);
    k_att<<<dim3(EE / 8, 3), 256>>>(pri, pri_cau);
    k_soft<<<(3 * NN * HH + 255) / 256, 256>>>();
    k_agg<<<(NN + 7) / 8, 256>>>(comb_pri, out);
}

// round 5
// speedup vs baseline: 1.6926x; 1.6926x over previous
#include <cuda_runtime.h>
#include <cuda_bf16.h>
#include <cstdint>

#define NN 20000
#define EE 160000
#define HH 8
#define DKK 32
#define DD 256

// ---------------- scratch (static device globals; no allocation) ----------------
__device__ float g_k[NN * DD];
__device__ float g_q[NN * DD];
__device__ float g_v[NN * DD];
__device__ float g_mk[NN * DD];
__device__ float g_val[3][NN * DD];
__device__ float g_cval[3][NN * DD];
__device__ float g_attb[3][EE * HH];
__device__ float g_cattb[3][EE * HH];
__device__ float g_inva[3][NN * HH];
__device__ float g_invc[3][NN * HH];
__device__ int   g_cnt[3][NN];
__device__ int   g_cur[3][NN];
__device__ int   g_off[3][NN + 1];
__device__ int   g_ssrc[3][EE];
__device__ int   g_sdst[3][EE];
// split-bf16 operands for the tensor-core GEMM
__device__ __nv_bfloat16 g_xh[NN * DD];
__device__ __nv_bfloat16 g_xl[NN * DD];
__device__ __nv_bfloat16 g_wh[3 * 256 * 256];   // [n'=mat*256+n][k] n-major
__device__ __nv_bfloat16 g_wl[3 * 256 * 256];

// ---------------- K0a: convert x to hi/lo bf16 ---------------------------------
__global__ void k_cvt_x(const float* __restrict__ x)
{
    int i = blockIdx.x * 256 + threadIdx.x;
    if (i < NN * DD) {
        float v = x[i];
        __nv_bfloat16 h = __float2bfloat16(v);
        g_xh[i] = h;
        g_xl[i] = __float2bfloat16(v - __bfloat162float(h));
    }
}

// ---------------- K0b: convert + transpose W to n-major hi/lo bf16 -------------
__global__ void k_cvt_w(const float* __restrict__ Wk,
                        const float* __restrict__ Wq,
                        const float* __restrict__ Wv)
{
    int i = blockIdx.x * 256 + threadIdx.x;
    if (i >= 3 * 256 * 256) return;
    int mat = i >> 16;
    int rem = i & 65535;
    int kk = rem >> 8;        // consecutive threads vary n -> coalesced read
    int n  = rem & 255;
    const float* W = (mat == 0) ? Wk : ((mat == 1) ? Wq : Wv);
    float v = W[kk * 256 + n];
    __nv_bfloat16 h = __float2bfloat16(v);
    int o = (mat * 256 + n) * 256 + kk;
    g_wh[o] = h;
    g_wl[o] = __float2bfloat16(v - __bfloat162float(h));
}

// ---------------- K1: tensor-core QKV GEMM (split bf16, fp32 acc) --------------
__device__ __forceinline__ void mma16816(float* c, const uint32_t* a, const uint32_t* b)
{
    asm volatile(
        "mma.sync.aligned.m16n8k16.row.col.f32.bf16.bf16.f32 "
        "{%0,%1,%2,%3}, {%4,%5,%6,%7}, {%8,%9}, {%0,%1,%2,%3};\n"
        : "+f"(c[0]), "+f"(c[1]), "+f"(c[2]), "+f"(c[3])
        : "r"(a[0]), "r"(a[1]), "r"(a[2]), "r"(a[3]), "r"(b[0]), "r"(b[1]));
}

#define ASTR 40   // padded bf16 stride (80B) -> conflict-free frag loads

__global__ __launch_bounds__(256) void k_gemm_tc(
    const float* __restrict__ bk,
    const float* __restrict__ bq,
    const float* __restrict__ bv)
{
    __shared__ __align__(16) __nv_bfloat16 sAh[128][ASTR];
    __shared__ __align__(16) __nv_bfloat16 sAl[128][ASTR];
    __shared__ __align__(16) __nv_bfloat16 sBh[64][ASTR];
    __shared__ __align__(16) __nv_bfloat16 sBl[64][ASTR];

    int bm = blockIdx.x * 128;
    int by = blockIdx.y;                  // 0..11 ; global n0 = by*64
    int mat = by >> 2;

    int tid  = threadIdx.x;
    int wid  = tid >> 5;
    int lane = tid & 31;
    int wm = wid & 3;                     // 4 warps over M (32 rows each)
    int wn = wid >> 2;                    // 2 warps over N (32 cols each)
    int g = lane >> 2, t = lane & 3;

    float acc[2][4][4];
#pragma unroll
    for (int a = 0; a < 2; a++)
#pragma unroll
        for (int b = 0; b < 4; b++)
#pragma unroll
            for (int c = 0; c < 4; c++) acc[a][b][c] = 0.f;

    for (int stage = 0; stage < 8; stage++) {
        int k0 = stage * 32;
        // load A tile (128x32 hi+lo)
        for (int idx = tid; idx < 128 * 8; idx += 256) {
            int row = idx >> 3, c4 = (idx & 7) * 4;
            int m = bm + row;
            uint2 vh = make_uint2(0u, 0u), vl = make_uint2(0u, 0u);
            if (m < NN) {
                vh = *(const uint2*)&g_xh[m * 256 + k0 + c4];
                vl = *(const uint2*)&g_xl[m * 256 + k0 + c4];
            }
            *(uint2*)&sAh[row][c4] = vh;
            *(uint2*)&sAl[row][c4] = vl;
        }
        // load B tile (64x32 hi+lo), rows are n' = by*64 + row
        for (int idx = tid; idx < 64 * 8; idx += 256) {
            int row = idx >> 3, c4 = (idx & 7) * 4;
            int np = by * 64 + row;
            *(uint2*)&sBh[row][c4] = *(const uint2*)&g_wh[np * 256 + k0 + c4];
            *(uint2*)&sBl[row][c4] = *(const uint2*)&g_wl[np * 256 + k0 + c4];
        }
        __syncthreads();

#pragma unroll
        for (int ks = 0; ks < 32; ks += 16) {
            uint32_t ah[2][4], al[2][4], bh[4][2], bl[4][2];
#pragma unroll
            for (int mt = 0; mt < 2; mt++) {
                int r0 = wm * 32 + mt * 16 + g;
                ah[mt][0] = *(const uint32_t*)&sAh[r0][ks + t * 2];
                ah[mt][1] = *(const uint32_t*)&sAh[r0 + 8][ks + t * 2];
                ah[mt][2] = *(const uint32_t*)&sAh[r0][ks + t * 2 + 8];
                ah[mt][3] = *(const uint32_t*)&sAh[r0 + 8][ks + t * 2 + 8];
                al[mt][0] = *(const uint32_t*)&sAl[r0][ks + t * 2];
                al[mt][1] = *(const uint32_t*)&sAl[r0 + 8][ks + t * 2];
                al[mt][2] = *(const uint32_t*)&sAl[r0][ks + t * 2 + 8];
                al[mt][3] = *(const uint32_t*)&sAl[r0 + 8][ks + t * 2 + 8];
            }
#pragma unroll
            for (int nt = 0; nt < 4; nt++) {
                int r0 = wn * 32 + nt * 8 + g;
                bh[nt][0] = *(const uint32_t*)&sBh[r0][ks + t * 2];
                bh[nt][1] = *(const uint32_t*)&sBh[r0][ks + t * 2 + 8];
                bl[nt][0] = *(const uint32_t*)&sBl[r0][ks + t * 2];
                bl[nt][1] = *(const uint32_t*)&sBl[r0][ks + t * 2 + 8];
            }
#pragma unroll
            for (int mt = 0; mt < 2; mt++)
#pragma unroll
                for (int nt = 0; nt < 4; nt++) {
                    mma16816(acc[mt][nt], ah[mt], bh[nt]);
                    mma16816(acc[mt][nt], ah[mt], bl[nt]);
                    mma16816(acc[mt][nt], al[mt], bh[nt]);
                }
        }
        __syncthreads();
    }

    const float* bias = (mat == 0) ? bk : ((mat == 1) ? bq : bv);
    float*       outp = (mat == 0) ? g_k : ((mat == 1) ? g_q : g_v);
    int nbase = (by & 3) * 64 + wn * 32;

#pragma unroll
    for (int mt = 0; mt < 2; mt++) {
        int m0 = bm + wm * 32 + mt * 16 + g;
#pragma unroll
        for (int nt = 0; nt < 4; nt++) {
            int col = nbase + nt * 8 + t * 2;
            float2 bb = *(const float2*)&bias[col];
            if (m0 < NN) {
                float2 o = make_float2(acc[mt][nt][0] + bb.x, acc[mt][nt][1] + bb.y);
                *(float2*)&outp[m0 * 256 + col] = o;
            }
            if (m0 + 8 < NN) {
                float2 o = make_float2(acc[mt][nt][2] + bb.x, acc[mt][nt][3] + bb.y);
                *(float2*)&outp[(m0 + 8) * 256 + col] = o;
            }
        }
    }
}

// ---------------- K2: per-node 32x32 head transforms ---------------------------
__device__ __forceinline__ void matvec32(const float* __restrict__ M,
                                         const float xv[32], float acc[32])
{
#pragma unroll
    for (int f = 0; f < 32; f++) acc[f] = 0.f;
#pragma unroll
    for (int d = 0; d < 32; d++) {
        float xd = xv[d];
#pragma unroll
        for (int f4 = 0; f4 < 8; f4++) {
            float4 m4 = *(const float4*)&M[d * 32 + f4 * 4];
            acc[f4 * 4 + 0] = fmaf(xd, m4.x, acc[f4 * 4 + 0]);
            acc[f4 * 4 + 1] = fmaf(xd, m4.y, acc[f4 * 4 + 1]);
            acc[f4 * 4 + 2] = fmaf(xd, m4.z, acc[f4 * 4 + 2]);
            acc[f4 * 4 + 3] = fmaf(xd, m4.w, acc[f4 * 4 + 3]);
        }
    }
}

__device__ __forceinline__ void store32(float* __restrict__ p, const float acc[32])
{
#pragma unroll
    for (int f4 = 0; f4 < 8; f4++) {
        float4 t = make_float4(acc[f4 * 4], acc[f4 * 4 + 1], acc[f4 * 4 + 2], acc[f4 * 4 + 3]);
        *(float4*)&p[f4 * 4] = t;
    }
}

__global__ __launch_bounds__(256) void k_transform(
    const float* __restrict__ msg,
    const float* __restrict__ msg_cau,
    const float* __restrict__ cau_filter,
    const float* __restrict__ time_emb,
    const int* __restrict__ cau_type)
{
    __shared__ float sMSG[3 * 1024];
    __shared__ float sMSGC[3 * 1024];
    __shared__ float sCF[3 * 1024];
    __shared__ float sTE[32];

    int h = blockIdx.y;
    int tid = threadIdx.x;
    for (int i = tid; i < 3 * 1024; i += 256) {
        int e = i >> 10, r = i & 1023;
        sMSG[i]  = msg[(e * 8 + h) * 1024 + r];
        sMSGC[i] = msg_cau[(e * 8 + h) * 1024 + r];
        sCF[i]   = cau_filter[(e * 8 + h) * 1024 + r];
    }
    if (tid < 32) sTE[tid] = time_emb[h * 32 + tid];
    __syncthreads();

    int node = blockIdx.x * 256 + tid;
    if (node >= NN) return;

    float xv[32], acc[32];
    const float* kr = &g_k[node * 256 + h * 32];
#pragma unroll
    for (int d4 = 0; d4 < 8; d4++) {
        float4 t = *(const float4*)&kr[d4 * 4];
        xv[d4 * 4 + 0] = t.x; xv[d4 * 4 + 1] = t.y;
        xv[d4 * 4 + 2] = t.z; xv[d4 * 4 + 3] = t.w;
    }
    int ct = cau_type[node];
    matvec32(&sCF[ct * 1024], xv, acc);
    store32(&g_mk[node * 256 + h * 32], acc);

    const float* vr = &g_v[node * 256 + h * 32];
#pragma unroll
    for (int d4 = 0; d4 < 8; d4++) {
        float4 t = *(const float4*)&vr[d4 * 4];
        xv[d4 * 4 + 0] = t.x; xv[d4 * 4 + 1] = t.y;
        xv[d4 * 4 + 2] = t.z; xv[d4 * 4 + 3] = t.w;
    }
    for (int e = 0; e < 3; e++) {
        matvec32(&sMSG[e * 1024], xv, acc);
        store32(&g_val[e][node * 256 + h * 32], acc);
    }
#pragma unroll
    for (int d = 0; d < 32; d++) xv[d] += sTE[d];
    for (int e = 0; e < 3; e++) {
        matvec32(&sMSGC[e * 1024], xv, acc);
        store32(&g_cval[e][node * 256 + h * 32], acc);
    }
}

// ---------------- K3: CSR build ------------------------------------------------
__global__ void k_zero()
{
    int i = blockIdx.x * 256 + threadIdx.x;
    if (i < 3 * NN) {
        ((int*)g_cnt)[i] = 0;
        ((int*)g_cur)[i] = 0;
    }
}

__global__ void k_count(const int* __restrict__ dst)
{
    int i = blockIdx.x * 256 + threadIdx.x;
    if (i < 3 * EE) {
        int e = i / EE;
        atomicAdd(&g_cnt[e][dst[i]], 1);
    }
}

__global__ __launch_bounds__(1024) void k_scan()
{
    __shared__ int s[1024];
    int t = threadIdx.x;
    for (int e = 0; e < 3; e++) {
        int carry = 0;
        if (t == 0) g_off[e][0] = 0;
        for (int base = 0; base < NN; base += 1024) {
            int v = (base + t < NN) ? g_cnt[e][base + t] : 0;
            s[t] = v;
            __syncthreads();
            for (int ofs = 1; ofs < 1024; ofs <<= 1) {
                int add = (t >= ofs) ? s[t - ofs] : 0;
                __syncthreads();
                s[t] += add;
                __syncthreads();
            }
            if (base + t < NN) g_off[e][base + t + 1] = carry + s[t];
            carry += s[1023];
            __syncthreads();
        }
    }
}

__global__ void k_scatter(const int* __restrict__ src, const int* __restrict__ dst)
{
    int i = blockIdx.x * 256 + threadIdx.x;
    if (i < 3 * EE) {
        int e = i / EE;
        int d = dst[i];
        int pos = g_off[e][d] + atomicAdd(&g_cur[e][d], 1);
        g_ssrc[e][pos] = src[i];
        g_sdst[e][pos] = d;
    }
}

// ---------------- K4: edge logits (warp per edge) ------------------------------
__global__ __launch_bounds__(256) void k_att(const float* __restrict__ pri,
                                             const float* __restrict__ pri_cau)
{
    int e = blockIdx.y;
    int w = blockIdx.x * 8 + (threadIdx.x >> 5);
    int l = threadIdx.x & 31;
    if (w >= EE) return;

    int s = g_ssrc[e][w];
    int d = g_sdst[e][w];

    const float* qp = &g_q[d * 256 + l * 8];
    const float* kp = &g_k[s * 256 + l * 8];
    const float* mp = &g_mk[s * 256 + l * 8];

    float4 q0 = *(const float4*)qp,        q1 = *(const float4*)(qp + 4);
    float4 k0 = *(const float4*)kp,        k1 = *(const float4*)(kp + 4);
    float4 m0 = *(const float4*)mp,        m1 = *(const float4*)(mp + 4);

    float pa = q0.x * k0.x + q0.y * k0.y + q0.z * k0.z + q0.w * k0.w
             + q1.x * k1.x + q1.y * k1.y + q1.z * k1.z + q1.w * k1.w;
    float pc = q0.x * m0.x + q0.y * m0.y + q0.z * m0.z + q0.w * m0.w
             + q1.x * m1.x + q1.y * m1.y + q1.z * m1.z + q1.w * m1.w;

    pa += __shfl_xor_sync(0xffffffffu, pa, 1);
    pa += __shfl_xor_sync(0xffffffffu, pa, 2);
    pc += __shfl_xor_sync(0xffffffffu, pc, 1);
    pc += __shfl_xor_sync(0xffffffffu, pc, 2);

    const float inv_sqrt = 0.17677669529663687f;  // 1/sqrt(32)
    float av = __shfl_sync(0xffffffffu, pa, (l & 7) * 4);
    float cv = __shfl_sync(0xffffffffu, pc, (l & 7) * 4);

    if (l < 8) {
        g_attb[e][w * 8 + l] = av * pri[e * 8 + l] * inv_sqrt;
    } else if (l < 16) {
        int h = l - 8;
        g_cattb[e][w * 8 + h] = cv * pri_cau[e * 8 + h] * inv_sqrt;
    }
}

// ---------------- K5: segment softmax ------------------------------------------
__global__ void k_soft()
{
    int i = blockIdx.x * 256 + threadIdx.x;
    if (i >= 3 * NN * HH) return;
    int e = i / (NN * HH);
    int rem = i - e * (NN * HH);
    int d = rem >> 3;
    int h = rem & 7;

    int st = g_off[e][d], en = g_off[e][d + 1];
    float m = -1e30f, m2 = -1e30f;
    for (int p = st; p < en; p++) {
        m  = fmaxf(m,  g_attb[e][p * 8 + h]);
        m2 = fmaxf(m2, g_cattb[e][p * 8 + h]);
    }
    float s = 0.f, s2 = 0.f;
    for (int p = st; p < en; p++) {
        float w  = __expf(g_attb[e][p * 8 + h] - m);
        float w2 = __expf(g_cattb[e][p * 8 + h] - m2);
        g_attb[e][p * 8 + h] = w;
        g_cattb[e][p * 8 + h] = w2;
        s += w; s2 += w2;
    }
    g_inva[e][d * 8 + h] = (en > st) ? 1.0f / s  : 0.0f;
    g_invc[e][d * 8 + h] = (en > st) ? 1.0f / s2 : 0.0f;
}

// ---------------- K6: aggregation (warp per dst node) --------------------------
__global__ __launch_bounds__(256) void k_agg(const float* __restrict__ comb_pri,
                                             float* __restrict__ out)
{
    int d = blockIdx.x * 8 + (threadIdx.x >> 5);
    int l = threadIdx.x & 31;
    if (d >= NN) return;

    float accO[8];
#pragma unroll
    for (int r = 0; r < 8; r++) accO[r] = 0.f;

    for (int e = 0; e < 3; e++) {
        int st = g_off[e][d], en = g_off[e][d + 1];
        float inv = 0.f;
        if (l < 8)        inv = g_inva[e][d * 8 + l];
        else if (l < 16)  inv = g_invc[e][d * 8 + (l - 8)];

        float aH[8], aC[8];
#pragma unroll
        for (int r = 0; r < 8; r++) { aH[r] = 0.f; aC[r] = 0.f; }

        for (int p = st; p < en; p++) {
            int s = g_ssrc[e][p];
            float wl = 0.f;
            if (l < 8)        wl = g_attb[e][p * 8 + l];
            else if (l < 16)  wl = g_cattb[e][p * 8 + (l - 8)];
            wl *= inv;

            const float* vp = &g_val[e][s * 256 + l];
            const float* cp = &g_cval[e][s * 256 + l];
#pragma unroll
            for (int r = 0; r < 8; r++) {
                float wr = __shfl_sync(0xffffffffu, wl, r);
                float cr = __shfl_sync(0xffffffffu, wl, r + 8);
                aH[r] = fmaf(wr, vp[r * 32], aH[r]);
                aC[r] = fmaf(cr, cp[r * 32], aC[r]);
            }
        }
#pragma unroll
        for (int r = 0; r < 8; r++) {
            float cpv = comb_pri[(e * 8 + r) * 32 + l];
            accO[r] += aH[r] + aC[r] * cpv;
        }
    }
#pragma unroll
    for (int r = 0; r < 8; r++)
        out[d * 256 + r * 32 + l] = fmaxf(accO[r] * (1.0f / 3.0f), 0.0f);
}

// ---------------- launch -------------------------------------------------------
extern "C" void kernel_launch(void* const* d_in, const int* in_sizes, int n_in,
                              void* d_out, int out_size)
{
    const float* x          = (const float*)d_in[0];
    const float* Wk         = (const float*)d_in[1];
    const float* bk         = (const float*)d_in[2];
    const float* Wq         = (const float*)d_in[3];
    const float* bq         = (const float*)d_in[4];
    const float* Wv         = (const float*)d_in[5];
    const float* bv         = (const float*)d_in[6];
    const float* pri        = (const float*)d_in[7];
    const float* msg        = (const float*)d_in[8];
    const float* pri_cau    = (const float*)d_in[9];
    const float* msg_cau    = (const float*)d_in[10];
    const float* comb_pri   = (const float*)d_in[11];
    const float* cau_filter = (const float*)d_in[12];
    const float* time_emb   = (const float*)d_in[13];
    const int*   cau_type   = (const int*)d_in[14];
    const int*   src        = (const int*)d_in[15];
    const int*   dst        = (const int*)d_in[16];
    float* out = (float*)d_out;

    k_cvt_x<<<(NN * DD + 255) / 256, 256>>>(x);
    k_cvt_w<<<(3 * 256 * 256 + 255) / 256, 256>>>(Wk, Wq, Wv);
    k_gemm_tc<<<dim3((NN + 127) / 128, 12), 256>>>(bk, bq, bv);
    k_transform<<<dim3((NN + 255) / 256, HH), 256>>>(msg, msg_cau, cau_filter,
                                                     time_emb, cau_type);
    k_zero<<<(3 * NN + 255) / 256, 256>>>();
    k_count<<<(3 * EE + 255) / 256, 256>>>(dst);
    k_scan<<<1, 1024>>>();
    k_scatter<<<(3 * EE + 255) / 256, 256>>>(src, dst);
    k_att<<<dim3(EE / 8, 3), 256>>>(pri, pri_cau);
    k_soft<<<(3 * NN * HH + 255) / 256, 256>>>();
    k_agg<<<(NN + 7) / 8, 256>>>(comb_pri, out);
}

// round 6
// speedup vs baseline: 1.9568x; 1.1561x over previous
#include <cuda_runtime.h>
#include <cuda_bf16.h>
#include <cstdint>

#define NN 20000
#define EE 160000
#define HH 8
#define DKK 32
#define DD 256

// ---------------- scratch (static device globals; no allocation) ----------------
__device__ float g_k[NN * DD];
__device__ float g_q[NN * DD];
__device__ float g_v[NN * DD];
__device__ float g_mk[NN * DD];
__device__ float g_val[3][NN * DD];
__device__ float g_cval[3][NN * DD];
__device__ float g_attb[3][EE * HH];
__device__ float g_cattb[3][EE * HH];
__device__ float g_inva[3][NN * HH];
__device__ float g_invc[3][NN * HH];
__device__ int   g_cnt[3][NN];
__device__ int   g_cur[3][NN];
__device__ int   g_off[3][NN + 1];
__device__ int   g_ssrc[3][EE];
__device__ int   g_sdst[3][EE];
// split-bf16 operands for the tensor-core GEMM
__device__ __nv_bfloat16 g_xh[NN * DD];
__device__ __nv_bfloat16 g_xl[NN * DD];
__device__ __nv_bfloat16 g_wh[3 * 256 * 256];   // [n'=mat*256+n][k] n-major
__device__ __nv_bfloat16 g_wl[3 * 256 * 256];
// split-bf16 k/v for the transform tensor-core kernel
__device__ __nv_bfloat16 g_kh[NN * DD];
__device__ __nv_bfloat16 g_kl[NN * DD];
__device__ __nv_bfloat16 g_vh[NN * DD];
__device__ __nv_bfloat16 g_vl[NN * DD];
// transform B operand: [h][n'<288][k=32]; n' 0-95 CF(ct), 96-191 MSG(e), 192-287 MSGC(e)
__device__ __nv_bfloat16 g_mbh[HH * 288 * 32];
__device__ __nv_bfloat16 g_mbl[HH * 288 * 32];
__device__ float g_cvbias[3 * HH * 32];          // te @ msgc per (e,h,f)

// ---------------- K0a: convert x to hi/lo bf16 ---------------------------------
__global__ void k_cvt_x(const float* __restrict__ x)
{
    int i = blockIdx.x * 256 + threadIdx.x;
    if (i < NN * DD) {
        float v = x[i];
        __nv_bfloat16 h = __float2bfloat16(v);
        g_xh[i] = h;
        g_xl[i] = __float2bfloat16(v - __bfloat162float(h));
    }
}

// ---------------- K0b: convert + transpose W to n-major hi/lo bf16 -------------
__global__ void k_cvt_w(const float* __restrict__ Wk,
                        const float* __restrict__ Wq,
                        const float* __restrict__ Wv)
{
    int i = blockIdx.x * 256 + threadIdx.x;
    if (i >= 3 * 256 * 256) return;
    int mat = i >> 16;
    int rem = i & 65535;
    int kk = rem >> 8;
    int n  = rem & 255;
    const float* W = (mat == 0) ? Wk : ((mat == 1) ? Wq : Wv);
    float v = W[kk * 256 + n];
    __nv_bfloat16 h = __float2bfloat16(v);
    int o = (mat * 256 + n) * 256 + kk;
    g_wh[o] = h;
    g_wl[o] = __float2bfloat16(v - __bfloat162float(h));
}

// ---------------- K0c: convert transform matrices to n-major hi/lo bf16 --------
__global__ void k_cvt_m(const float* __restrict__ msg,
                        const float* __restrict__ msg_cau,
                        const float* __restrict__ cau_filter)
{
    int i = blockIdx.x * 256 + threadIdx.x;
    if (i >= HH * 288 * 32) return;
    int h  = i / (288 * 32);
    int rem = i - h * (288 * 32);
    int np = rem >> 5;           // n' 0..287
    int d  = rem & 31;
    float v;
    if (np < 96) {
        int ct = np >> 5, f = np & 31;
        v = cau_filter[((ct * 8 + h) << 10) + d * 32 + f];
    } else if (np < 192) {
        int e = (np - 96) >> 5, f = np & 31;
        v = msg[((e * 8 + h) << 10) + d * 32 + f];
    } else {
        int e = (np - 192) >> 5, f = np & 31;
        v = msg_cau[((e * 8 + h) << 10) + d * 32 + f];
    }
    __nv_bfloat16 hh = __float2bfloat16(v);
    g_mbh[i] = hh;
    g_mbl[i] = __float2bfloat16(v - __bfloat162float(hh));
}

// ---------------- K0d: cval bias = te @ msgc ------------------------------------
__global__ void k_bias(const float* __restrict__ time_emb,
                       const float* __restrict__ msg_cau)
{
    int e = blockIdx.x;
    int t = threadIdx.x;            // 256 = 8h * 32f
    int h = t >> 5, f = t & 31;
    float s = 0.f;
#pragma unroll
    for (int d = 0; d < 32; d++)
        s = fmaf(time_emb[h * 32 + d], msg_cau[((e * 8 + h) << 10) + d * 32 + f], s);
    g_cvbias[(e * 8 + h) * 32 + f] = s;
}

// ---------------- K0e: split k/v to hi/lo bf16 ----------------------------------
__global__ void k_cvt_kv()
{
    int i = blockIdx.x * 256 + threadIdx.x;
    if (i < NN * DD) {
        float a = g_k[i];
        __nv_bfloat16 h = __float2bfloat16(a);
        g_kh[i] = h;
        g_kl[i] = __float2bfloat16(a - __bfloat162float(h));
        float b = g_v[i];
        __nv_bfloat16 h2 = __float2bfloat16(b);
        g_vh[i] = h2;
        g_vl[i] = __float2bfloat16(b - __bfloat162float(h2));
    }
}

// ---------------- shared mma helper ---------------------------------------------
__device__ __forceinline__ void mma16816(float* c, const uint32_t* a, const uint32_t* b)
{
    asm volatile(
        "mma.sync.aligned.m16n8k16.row.col.f32.bf16.bf16.f32 "
        "{%0,%1,%2,%3}, {%4,%5,%6,%7}, {%8,%9}, {%0,%1,%2,%3};\n"
        : "+f"(c[0]), "+f"(c[1]), "+f"(c[2]), "+f"(c[3])
        : "r"(a[0]), "r"(a[1]), "r"(a[2]), "r"(a[3]), "r"(b[0]), "r"(b[1]));
}

#define ASTR 40   // padded bf16 stride (80B) -> conflict-free frag loads

// ---------------- K1: tensor-core QKV GEMM (split bf16, fp32 acc) ---------------
__global__ __launch_bounds__(256) void k_gemm_tc(
    const float* __restrict__ bk,
    const float* __restrict__ bq,
    const float* __restrict__ bv)
{
    __shared__ __align__(16) __nv_bfloat16 sAh[128][ASTR];
    __shared__ __align__(16) __nv_bfloat16 sAl[128][ASTR];
    __shared__ __align__(16) __nv_bfloat16 sBh[64][ASTR];
    __shared__ __align__(16) __nv_bfloat16 sBl[64][ASTR];

    int bm = blockIdx.x * 128;
    int by = blockIdx.y;
    int mat = by >> 2;

    int tid  = threadIdx.x;
    int wid  = tid >> 5;
    int lane = tid & 31;
    int wm = wid & 3;
    int wn = wid >> 2;
    int g = lane >> 2, t = lane & 3;

    float acc[2][4][4];
#pragma unroll
    for (int a = 0; a < 2; a++)
#pragma unroll
        for (int b = 0; b < 4; b++)
#pragma unroll
            for (int c = 0; c < 4; c++) acc[a][b][c] = 0.f;

    for (int stage = 0; stage < 8; stage++) {
        int k0 = stage * 32;
        for (int idx = tid; idx < 128 * 8; idx += 256) {
            int row = idx >> 3, c4 = (idx & 7) * 4;
            int m = bm + row;
            uint2 vh = make_uint2(0u, 0u), vl = make_uint2(0u, 0u);
            if (m < NN) {
                vh = *(const uint2*)&g_xh[m * 256 + k0 + c4];
                vl = *(const uint2*)&g_xl[m * 256 + k0 + c4];
            }
            *(uint2*)&sAh[row][c4] = vh;
            *(uint2*)&sAl[row][c4] = vl;
        }
        for (int idx = tid; idx < 64 * 8; idx += 256) {
            int row = idx >> 3, c4 = (idx & 7) * 4;
            int np = by * 64 + row;
            *(uint2*)&sBh[row][c4] = *(const uint2*)&g_wh[np * 256 + k0 + c4];
            *(uint2*)&sBl[row][c4] = *(const uint2*)&g_wl[np * 256 + k0 + c4];
        }
        __syncthreads();

#pragma unroll
        for (int ks = 0; ks < 32; ks += 16) {
            uint32_t ah[2][4], al[2][4], bh[4][2], bl[4][2];
#pragma unroll
            for (int mt = 0; mt < 2; mt++) {
                int r0 = wm * 32 + mt * 16 + g;
                ah[mt][0] = *(const uint32_t*)&sAh[r0][ks + t * 2];
                ah[mt][1] = *(const uint32_t*)&sAh[r0 + 8][ks + t * 2];
                ah[mt][2] = *(const uint32_t*)&sAh[r0][ks + t * 2 + 8];
                ah[mt][3] = *(const uint32_t*)&sAh[r0 + 8][ks + t * 2 + 8];
                al[mt][0] = *(const uint32_t*)&sAl[r0][ks + t * 2];
                al[mt][1] = *(const uint32_t*)&sAl[r0 + 8][ks + t * 2];
                al[mt][2] = *(const uint32_t*)&sAl[r0][ks + t * 2 + 8];
                al[mt][3] = *(const uint32_t*)&sAl[r0 + 8][ks + t * 2 + 8];
            }
#pragma unroll
            for (int nt = 0; nt < 4; nt++) {
                int r0 = wn * 32 + nt * 8 + g;
                bh[nt][0] = *(const uint32_t*)&sBh[r0][ks + t * 2];
                bh[nt][1] = *(const uint32_t*)&sBh[r0][ks + t * 2 + 8];
                bl[nt][0] = *(const uint32_t*)&sBl[r0][ks + t * 2];
                bl[nt][1] = *(const uint32_t*)&sBl[r0][ks + t * 2 + 8];
            }
#pragma unroll
            for (int mt = 0; mt < 2; mt++)
#pragma unroll
                for (int nt = 0; nt < 4; nt++) {
                    mma16816(acc[mt][nt], ah[mt], bh[nt]);
                    mma16816(acc[mt][nt], ah[mt], bl[nt]);
                    mma16816(acc[mt][nt], al[mt], bh[nt]);
                }
        }
        __syncthreads();
    }

    const float* bias = (mat == 0) ? bk : ((mat == 1) ? bq : bv);
    float*       outp = (mat == 0) ? g_k : ((mat == 1) ? g_q : g_v);
    int nbase = (by & 3) * 64 + wn * 32;

#pragma unroll
    for (int mt = 0; mt < 2; mt++) {
        int m0 = bm + wm * 32 + mt * 16 + g;
#pragma unroll
        for (int nt = 0; nt < 4; nt++) {
            int col = nbase + nt * 8 + t * 2;
            float2 bb = *(const float2*)&bias[col];
            if (m0 < NN) {
                float2 o = make_float2(acc[mt][nt][0] + bb.x, acc[mt][nt][1] + bb.y);
                *(float2*)&outp[m0 * 256 + col] = o;
            }
            if (m0 + 8 < NN) {
                float2 o = make_float2(acc[mt][nt][2] + bb.x, acc[mt][nt][3] + bb.y);
                *(float2*)&outp[(m0 + 8) * 256 + col] = o;
            }
        }
    }
}

// ---------------- K2: tensor-core head transforms -------------------------------
// block = 128 nodes x 1 head; warps own m16 row tiles; B frags from global (L1).
__global__ __launch_bounds__(256) void k_transform_tc(const int* __restrict__ cau_type)
{
    __shared__ __align__(16) __nv_bfloat16 sKh[128][ASTR];
    __shared__ __align__(16) __nv_bfloat16 sKl[128][ASTR];
    __shared__ __align__(16) __nv_bfloat16 sVh[128][ASTR];
    __shared__ __align__(16) __nv_bfloat16 sVl[128][ASTR];
    __shared__ int sCT[128];

    int tile = blockIdx.x;
    int h    = blockIdx.y;
    int base = tile * 128;
    int tid  = threadIdx.x;
    int wid  = tid >> 5;
    int lane = tid & 31;
    int g = lane >> 2, t = lane & 3;

    // cooperative load of k/v hi/lo tiles (head h columns)
    for (int idx = tid; idx < 128 * 8; idx += 256) {
        int row = idx >> 3, c4 = (idx & 7) * 4;
        int m = base + row;
        uint2 kh = make_uint2(0u, 0u), kl = kh, vh = kh, vl = kh;
        if (m < NN) {
            int o = m * 256 + h * 32 + c4;
            kh = *(const uint2*)&g_kh[o];
            kl = *(const uint2*)&g_kl[o];
            vh = *(const uint2*)&g_vh[o];
            vl = *(const uint2*)&g_vl[o];
        }
        *(uint2*)&sKh[row][c4] = kh;
        *(uint2*)&sKl[row][c4] = kl;
        *(uint2*)&sVh[row][c4] = vh;
        *(uint2*)&sVl[row][c4] = vl;
    }
    if (tid < 128) {
        int m = base + tid;
        sCT[tid] = (m < NN) ? cau_type[m] : -1;
    }
    __syncthreads();

    // load A frags for this warp's m16 tile (rows wid*16 .. +15)
    int r0 = wid * 16 + g;
    uint32_t kAh[2][4], kAl[2][4], vAh[2][4], vAl[2][4];
#pragma unroll
    for (int ki = 0; ki < 2; ki++) {
        int ks = ki * 16;
        kAh[ki][0] = *(const uint32_t*)&sKh[r0][ks + t * 2];
        kAh[ki][1] = *(const uint32_t*)&sKh[r0 + 8][ks + t * 2];
        kAh[ki][2] = *(const uint32_t*)&sKh[r0][ks + t * 2 + 8];
        kAh[ki][3] = *(const uint32_t*)&sKh[r0 + 8][ks + t * 2 + 8];
        kAl[ki][0] = *(const uint32_t*)&sKl[r0][ks + t * 2];
        kAl[ki][1] = *(const uint32_t*)&sKl[r0 + 8][ks + t * 2];
        kAl[ki][2] = *(const uint32_t*)&sKl[r0][ks + t * 2 + 8];
        kAl[ki][3] = *(const uint32_t*)&sKl[r0 + 8][ks + t * 2 + 8];
        vAh[ki][0] = *(const uint32_t*)&sVh[r0][ks + t * 2];
        vAh[ki][1] = *(const uint32_t*)&sVh[r0 + 8][ks + t * 2];
        vAh[ki][2] = *(const uint32_t*)&sVh[r0][ks + t * 2 + 8];
        vAh[ki][3] = *(const uint32_t*)&sVh[r0 + 8][ks + t * 2 + 8];
        vAl[ki][0] = *(const uint32_t*)&sVl[r0][ks + t * 2];
        vAl[ki][1] = *(const uint32_t*)&sVl[r0 + 8][ks + t * 2];
        vAl[ki][2] = *(const uint32_t*)&sVl[r0][ks + t * 2 + 8];
        vAl[ki][3] = *(const uint32_t*)&sVl[r0 + 8][ks + t * 2 + 8];
    }

    int row0 = base + r0;            // output row for c0,c1
    int row1 = row0 + 8;             // output row for c2,c3
    int ct0 = sCT[r0];
    int ct1 = sCT[r0 + 8];
    const __nv_bfloat16* mbh = &g_mbh[h * 288 * 32];
    const __nv_bfloat16* mbl = &g_mbl[h * 288 * 32];

    // ---- phase 1: masked_k = k @ CF[ct], select variant per row ----
#pragma unroll
    for (int var = 0; var < 3; var++) {
#pragma unroll
        for (int nt = 0; nt < 4; nt++) {
            int np = var * 32 + nt * 8;           // absolute n'
            float acc[4] = {0.f, 0.f, 0.f, 0.f};
#pragma unroll
            for (int ki = 0; ki < 2; ki++) {
                int ks = ki * 16;
                uint32_t bh[2], bl[2];
                bh[0] = *(const uint32_t*)&mbh[(np + g) * 32 + ks + t * 2];
                bh[1] = *(const uint32_t*)&mbh[(np + g) * 32 + ks + t * 2 + 8];
                bl[0] = *(const uint32_t*)&mbl[(np + g) * 32 + ks + t * 2];
                bl[1] = *(const uint32_t*)&mbl[(np + g) * 32 + ks + t * 2 + 8];
                mma16816(acc, kAh[ki], bh);
                mma16816(acc, kAh[ki], bl);
                mma16816(acc, kAl[ki], bh);
            }
            int f = nt * 8 + t * 2;
            if (row0 < NN && ct0 == var)
                *(float2*)&g_mk[row0 * 256 + h * 32 + f] = make_float2(acc[0], acc[1]);
            if (row1 < NN && ct1 == var)
                *(float2*)&g_mk[row1 * 256 + h * 32 + f] = make_float2(acc[2], acc[3]);
        }
    }

    // ---- phase 2: val[e] = v @ MSG[e] ----
#pragma unroll
    for (int e = 0; e < 3; e++) {
#pragma unroll
        for (int nt = 0; nt < 4; nt++) {
            int np = 96 + e * 32 + nt * 8;
            float acc[4] = {0.f, 0.f, 0.f, 0.f};
#pragma unroll
            for (int ki = 0; ki < 2; ki++) {
                int ks = ki * 16;
                uint32_t bh[2], bl[2];
                bh[0] = *(const uint32_t*)&mbh[(np + g) * 32 + ks + t * 2];
                bh[1] = *(const uint32_t*)&mbh[(np + g) * 32 + ks + t * 2 + 8];
                bl[0] = *(const uint32_t*)&mbl[(np + g) * 32 + ks + t * 2];
                bl[1] = *(const uint32_t*)&mbl[(np + g) * 32 + ks + t * 2 + 8];
                mma16816(acc, vAh[ki], bh);
                mma16816(acc, vAh[ki], bl);
                mma16816(acc, vAl[ki], bh);
            }
            int f = nt * 8 + t * 2;
            if (row0 < NN)
                *(float2*)&g_val[e][row0 * 256 + h * 32 + f] = make_float2(acc[0], acc[1]);
            if (row1 < NN)
                *(float2*)&g_val[e][row1 * 256 + h * 32 + f] = make_float2(acc[2], acc[3]);
        }
    }

    // ---- phase 3: cval[e] = v @ MSGC[e] + (te @ MSGC[e]) ----
#pragma unroll
    for (int e = 0; e < 3; e++) {
#pragma unroll
        for (int nt = 0; nt < 4; nt++) {
            int np = 192 + e * 32 + nt * 8;
            float acc[4] = {0.f, 0.f, 0.f, 0.f};
#pragma unroll
            for (int ki = 0; ki < 2; ki++) {
                int ks = ki * 16;
                uint32_t bh[2], bl[2];
                bh[0] = *(const uint32_t*)&mbh[(np + g) * 32 + ks + t * 2];
                bh[1] = *(const uint32_t*)&mbh[(np + g) * 32 + ks + t * 2 + 8];
                bl[0] = *(const uint32_t*)&mbl[(np + g) * 32 + ks + t * 2];
                bl[1] = *(const uint32_t*)&mbl[(np + g) * 32 + ks + t * 2 + 8];
                mma16816(acc, vAh[ki], bh);
                mma16816(acc, vAh[ki], bl);
                mma16816(acc, vAl[ki], bh);
            }
            int f = nt * 8 + t * 2;
            float2 bb = *(const float2*)&g_cvbias[(e * 8 + h) * 32 + f];
            if (row0 < NN)
                *(float2*)&g_cval[e][row0 * 256 + h * 32 + f] =
                    make_float2(acc[0] + bb.x, acc[1] + bb.y);
            if (row1 < NN)
                *(float2*)&g_cval[e][row1 * 256 + h * 32 + f] =
                    make_float2(acc[2] + bb.x, acc[3] + bb.y);
        }
    }
}

// ---------------- K3: CSR build ------------------------------------------------
__global__ void k_zero()
{
    int i = blockIdx.x * 256 + threadIdx.x;
    if (i < 3 * NN) {
        ((int*)g_cnt)[i] = 0;
        ((int*)g_cur)[i] = 0;
    }
}

__global__ void k_count(const int* __restrict__ dst)
{
    int i = blockIdx.x * 256 + threadIdx.x;
    if (i < 3 * EE) {
        int e = i / EE;
        atomicAdd(&g_cnt[e][dst[i]], 1);
    }
}

__global__ __launch_bounds__(1024) void k_scan()
{
    __shared__ int s[1024];
    int t = threadIdx.x;
    for (int e = 0; e < 3; e++) {
        int carry = 0;
        if (t == 0) g_off[e][0] = 0;
        for (int base = 0; base < NN; base += 1024) {
            int v = (base + t < NN) ? g_cnt[e][base + t] : 0;
            s[t] = v;
            __syncthreads();
            for (int ofs = 1; ofs < 1024; ofs <<= 1) {
                int add = (t >= ofs) ? s[t - ofs] : 0;
                __syncthreads();
                s[t] += add;
                __syncthreads();
            }
            if (base + t < NN) g_off[e][base + t + 1] = carry + s[t];
            carry += s[1023];
            __syncthreads();
        }
    }
}

__global__ void k_scatter(const int* __restrict__ src, const int* __restrict__ dst)
{
    int i = blockIdx.x * 256 + threadIdx.x;
    if (i < 3 * EE) {
        int e = i / EE;
        int d = dst[i];
        int pos = g_off[e][d] + atomicAdd(&g_cur[e][d], 1);
        g_ssrc[e][pos] = src[i];
        g_sdst[e][pos] = d;
    }
}

// ---------------- K4: edge logits (warp per edge) ------------------------------
__global__ __launch_bounds__(256) void k_att(const float* __restrict__ pri,
                                             const float* __restrict__ pri_cau)
{
    int e = blockIdx.y;
    int w = blockIdx.x * 8 + (threadIdx.x >> 5);
    int l = threadIdx.x & 31;
    if (w >= EE) return;

    int s = g_ssrc[e][w];
    int d = g_sdst[e][w];

    const float* qp = &g_q[d * 256 + l * 8];
    const float* kp = &g_k[s * 256 + l * 8];
    const float* mp = &g_mk[s * 256 + l * 8];

    float4 q0 = *(const float4*)qp,        q1 = *(const float4*)(qp + 4);
    float4 k0 = *(const float4*)kp,        k1 = *(const float4*)(kp + 4);
    float4 m0 = *(const float4*)mp,        m1 = *(const float4*)(mp + 4);

    float pa = q0.x * k0.x + q0.y * k0.y + q0.z * k0.z + q0.w * k0.w
             + q1.x * k1.x + q1.y * k1.y + q1.z * k1.z + q1.w * k1.w;
    float pc = q0.x * m0.x + q0.y * m0.y + q0.z * m0.z + q0.w * m0.w
             + q1.x * m1.x + q1.y * m1.y + q1.z * m1.z + q1.w * m1.w;

    pa += __shfl_xor_sync(0xffffffffu, pa, 1);
    pa += __shfl_xor_sync(0xffffffffu, pa, 2);
    pc += __shfl_xor_sync(0xffffffffu, pc, 1);
    pc += __shfl_xor_sync(0xffffffffu, pc, 2);

    const float inv_sqrt = 0.17677669529663687f;  // 1/sqrt(32)
    float av = __shfl_sync(0xffffffffu, pa, (l & 7) * 4);
    float cv = __shfl_sync(0xffffffffu, pc, (l & 7) * 4);

    if (l < 8) {
        g_attb[e][w * 8 + l] = av * pri[e * 8 + l] * inv_sqrt;
    } else if (l < 16) {
        int h = l - 8;
        g_cattb[e][w * 8 + h] = cv * pri_cau[e * 8 + h] * inv_sqrt;
    }
}

// ---------------- K5: segment softmax ------------------------------------------
__global__ void k_soft()
{
    int i = blockIdx.x * 256 + threadIdx.x;
    if (i >= 3 * NN * HH) return;
    int e = i / (NN * HH);
    int rem = i - e * (NN * HH);
    int d = rem >> 3;
    int h = rem & 7;

    int st = g_off[e][d], en = g_off[e][d + 1];
    float m = -1e30f, m2 = -1e30f;
    for (int p = st; p < en; p++) {
        m  = fmaxf(m,  g_attb[e][p * 8 + h]);
        m2 = fmaxf(m2, g_cattb[e][p * 8 + h]);
    }
    float s = 0.f, s2 = 0.f;
    for (int p = st; p < en; p++) {
        float w  = __expf(g_attb[e][p * 8 + h] - m);
        float w2 = __expf(g_cattb[e][p * 8 + h] - m2);
        g_attb[e][p * 8 + h] = w;
        g_cattb[e][p * 8 + h] = w2;
        s += w; s2 += w2;
    }
    g_inva[e][d * 8 + h] = (en > st) ? 1.0f / s  : 0.0f;
    g_invc[e][d * 8 + h] = (en > st) ? 1.0f / s2 : 0.0f;
}

// ---------------- K6: aggregation (warp per dst node) --------------------------
__global__ __launch_bounds__(256) void k_agg(const float* __restrict__ comb_pri,
                                             float* __restrict__ out)
{
    int d = blockIdx.x * 8 + (threadIdx.x >> 5);
    int l = threadIdx.x & 31;
    if (d >= NN) return;

    float accO[8];
#pragma unroll
    for (int r = 0; r < 8; r++) accO[r] = 0.f;

    for (int e = 0; e < 3; e++) {
        int st = g_off[e][d], en = g_off[e][d + 1];
        float inv = 0.f;
        if (l < 8)        inv = g_inva[e][d * 8 + l];
        else if (l < 16)  inv = g_invc[e][d * 8 + (l - 8)];

        float aH[8], aC[8];
#pragma unroll
        for (int r = 0; r < 8; r++) { aH[r] = 0.f; aC[r] = 0.f; }

        for (int p = st; p < en; p++) {
            int s = g_ssrc[e][p];
            float wl = 0.f;
            if (l < 8)        wl = g_attb[e][p * 8 + l];
            else if (l < 16)  wl = g_cattb[e][p * 8 + (l - 8)];
            wl *= inv;

            const float* vp = &g_val[e][s * 256 + l];
            const float* cp = &g_cval[e][s * 256 + l];
#pragma unroll
            for (int r = 0; r < 8; r++) {
                float wr = __shfl_sync(0xffffffffu, wl, r);
                float cr = __shfl_sync(0xffffffffu, wl, r + 8);
                aH[r] = fmaf(wr, vp[r * 32], aH[r]);
                aC[r] = fmaf(cr, cp[r * 32], aC[r]);
            }
        }
#pragma unroll
        for (int r = 0; r < 8; r++) {
            float cpv = comb_pri[(e * 8 + r) * 32 + l];
            accO[r] += aH[r] + aC[r] * cpv;
        }
    }
#pragma unroll
    for (int r = 0; r < 8; r++)
        out[d * 256 + r * 32 + l] = fmaxf(accO[r] * (1.0f / 3.0f), 0.0f);
}

// ---------------- launch -------------------------------------------------------
extern "C" void kernel_launch(void* const* d_in, const int* in_sizes, int n_in,
                              void* d_out, int out_size)
{
    const float* x          = (const float*)d_in[0];
    const float* Wk         = (const float*)d_in[1];
    const float* bk         = (const float*)d_in[2];
    const float* Wq         = (const float*)d_in[3];
    const float* bq         = (const float*)d_in[4];
    const float* Wv         = (const float*)d_in[5];
    const float* bv         = (const float*)d_in[6];
    const float* pri        = (const float*)d_in[7];
    const float* msg        = (const float*)d_in[8];
    const float* pri_cau    = (const float*)d_in[9];
    const float* msg_cau    = (const float*)d_in[10];
    const float* comb_pri   = (const float*)d_in[11];
    const float* cau_filter = (const float*)d_in[12];
    const float* time_emb   = (const float*)d_in[13];
    const int*   cau_type   = (const int*)d_in[14];
    const int*   src        = (const int*)d_in[15];
    const int*   dst        = (const int*)d_in[16];
    float* out = (float*)d_out;

    k_cvt_x<<<(NN * DD + 255) / 256, 256>>>(x);
    k_cvt_w<<<(3 * 256 * 256 + 255) / 256, 256>>>(Wk, Wq, Wv);
    k_cvt_m<<<(HH * 288 * 32 + 255) / 256, 256>>>(msg, msg_cau, cau_filter);
    k_bias<<<3, 256>>>(time_emb, msg_cau);
    k_gemm_tc<<<dim3((NN + 127) / 128, 12), 256>>>(bk, bq, bv);
    k_cvt_kv<<<(NN * DD + 255) / 256, 256>>>();
    k_transform_tc<<<dim3((NN + 127) / 128, HH), 256>>>(cau_type);
    k_zero<<<(3 * NN + 255) / 256, 256>>>();
    k_count<<<(3 * EE + 255) / 256, 256>>>(dst);
    k_scan<<<1, 1024>>>();
    k_scatter<<<(3 * EE + 255) / 256, 256>>>(src, dst);
    k_att<<<dim3(EE / 8, 3), 256>>>(pri, pri_cau);
    k_soft<<<(3 * NN * HH + 255) / 256, 256>>>();
    k_agg<<<(NN + 7) / 8, 256>>>(comb_pri, out);
}

// round 8
// speedup vs baseline: 2.1139x; 1.0803x over previous
#include <cuda_runtime.h>
#include <cuda_bf16.h>
#include <cstdint>

#define NN 20000
#define EE 160000
#define HH 8
#define DKK 32
#define DD 256

// ---------------- scratch (static device globals; no allocation) ----------------
__device__ float g_k[NN * DD];
__device__ float g_q[NN * DD];
__device__ float g_v[NN * DD];
__device__ float g_qcf[NN * 3 * DD];           // qcf[d][ct][h*32+dd]
__device__ float g_sc[NN * HH * 192];          // [node][h][S1 e0..2 | S2 e0..2]
__device__ float g_attb[3][EE * HH];
__device__ float g_cattb[3][EE * HH];
__device__ float g_inva[3][NN * HH];
__device__ float g_invc[3][NN * HH];
__device__ int   g_cnt[3][NN];
__device__ int   g_cur[3][NN];
__device__ int   g_off[3][NN + 1];
__device__ int   g_ssrc[3][EE];
__device__ int   g_sdst[3][EE];
// split-bf16 operands
__device__ __nv_bfloat16 g_xh[NN * DD];
__device__ __nv_bfloat16 g_xl[NN * DD];
__device__ __nv_bfloat16 g_wh[3 * 256 * 256];  // [mat*256+n][k]
__device__ __nv_bfloat16 g_wl[3 * 256 * 256];
__device__ __nv_bfloat16 g_qh[NN * DD];        // q split (written by gemm epilogue)
__device__ __nv_bfloat16 g_ql[NN * DD];
__device__ __nv_bfloat16 g_cfbh[HH * 96 * 32]; // B for qcf: [h][ct*32+dd][f]
__device__ __nv_bfloat16 g_cfbl[HH * 96 * 32];
__device__ __nv_bfloat16 g_pbh[HH * 32 * 192]; // B for post: [h][f][k'=192]
__device__ __nv_bfloat16 g_pbl[HH * 32 * 192];
__device__ float g_bias2[3 * HH * 32];         // (te@msgc)*comb_pri

// ---------------- K0a: convert x to hi/lo bf16 ---------------------------------
__global__ void k_cvt_x(const float* __restrict__ x)
{
    int i = blockIdx.x * 256 + threadIdx.x;
    if (i < NN * DD) {
        float v = x[i];
        __nv_bfloat16 h = __float2bfloat16(v);
        g_xh[i] = h;
        g_xl[i] = __float2bfloat16(v - __bfloat162float(h));
    }
}

// ---------------- K0b: convert + transpose W ------------------------------------
__global__ void k_cvt_w(const float* __restrict__ Wk,
                        const float* __restrict__ Wq,
                        const float* __restrict__ Wv)
{
    int i = blockIdx.x * 256 + threadIdx.x;
    if (i >= 3 * 256 * 256) return;
    int mat = i >> 16;
    int rem = i & 65535;
    int kk = rem >> 8;
    int n  = rem & 255;
    const float* W = (mat == 0) ? Wk : ((mat == 1) ? Wq : Wv);
    float v = W[kk * 256 + n];
    __nv_bfloat16 h = __float2bfloat16(v);
    int o = (mat * 256 + n) * 256 + kk;
    g_wh[o] = h;
    g_wl[o] = __float2bfloat16(v - __bfloat162float(h));
}

// ---------------- K0c: prep transform/post B operands + bias --------------------
#define CFB_N (HH * 96 * 32)
#define PB_N  (HH * 32 * 192)
__global__ void k_prep(const float* __restrict__ msg,
                       const float* __restrict__ msg_cau,
                       const float* __restrict__ cau_filter,
                       const float* __restrict__ time_emb,
                       const float* __restrict__ comb_pri)
{
    int i = blockIdx.x * 256 + threadIdx.x;
    if (i < CFB_N) {
        int h = i / (96 * 32);
        int rem = i - h * (96 * 32);
        int np = rem >> 5, f = rem & 31;
        int ct = np >> 5, dd = np & 31;
        float v = cau_filter[((ct * 8 + h) << 10) + dd * 32 + f];
        __nv_bfloat16 hh = __float2bfloat16(v);
        g_cfbh[i] = hh;
        g_cfbl[i] = __float2bfloat16(v - __bfloat162float(hh));
    } else if (i < CFB_N + PB_N) {
        int j = i - CFB_N;
        int h = j / (32 * 192);
        int rem = j - h * (32 * 192);
        int n = rem / 192, kp = rem - n * 192;
        float v;
        if (kp < 96) {
            int e = kp >> 5, dd = kp & 31;
            v = msg[((e * 8 + h) << 10) + dd * 32 + n];
        } else {
            int kc = kp - 96;
            int e = kc >> 5, dd = kc & 31;
            v = msg_cau[((e * 8 + h) << 10) + dd * 32 + n]
              * comb_pri[(e * 8 + h) * 32 + n];
        }
        __nv_bfloat16 hh = __float2bfloat16(v);
        g_pbh[j] = hh;
        g_pbl[j] = __float2bfloat16(v - __bfloat162float(hh));
    } else if (i < CFB_N + PB_N + 3 * HH * 32) {
        int j = i - CFB_N - PB_N;     // (e*8+h)*32+f
        int eh = j >> 5, f = j & 31;
        int h = eh & 7;
        float s = 0.f;
#pragma unroll
        for (int d = 0; d < 32; d++)
            s = fmaf(time_emb[h * 32 + d], msg_cau[(eh << 10) + d * 32 + f], s);
        g_bias2[j] = s * comb_pri[eh * 32 + f];
    }
}

// ---------------- shared mma helper ---------------------------------------------
__device__ __forceinline__ void mma16816(float* c, const uint32_t* a, const uint32_t* b)
{
    asm volatile(
        "mma.sync.aligned.m16n8k16.row.col.f32.bf16.bf16.f32 "
        "{%0,%1,%2,%3}, {%4,%5,%6,%7}, {%8,%9}, {%0,%1,%2,%3};\n"
        : "+f"(c[0]), "+f"(c[1]), "+f"(c[2]), "+f"(c[3])
        : "r"(a[0]), "r"(a[1]), "r"(a[2]), "r"(a[3]), "r"(b[0]), "r"(b[1]));
}

__device__ __forceinline__ uint32_t pack_hi2(float a, float b)
{
    __nv_bfloat16 ha = __float2bfloat16(a), hb = __float2bfloat16(b);
    return ((uint32_t)__bfloat16_as_ushort(hb) << 16) | __bfloat16_as_ushort(ha);
}
__device__ __forceinline__ uint32_t pack_lo2(float a, float b)
{
    __nv_bfloat16 ha = __float2bfloat16(a), hb = __float2bfloat16(b);
    __nv_bfloat16 la = __float2bfloat16(a - __bfloat162float(ha));
    __nv_bfloat16 lb = __float2bfloat16(b - __bfloat162float(hb));
    return ((uint32_t)__bfloat16_as_ushort(lb) << 16) | __bfloat16_as_ushort(la);
}

#define ASTR 40

// ---------------- K1: tensor-core QKV GEMM --------------------------------------
__global__ __launch_bounds__(256) void k_gemm_tc(
    const float* __restrict__ bk,
    const float* __restrict__ bq,
    const float* __restrict__ bv)
{
    __shared__ __align__(16) __nv_bfloat16 sAh[128][ASTR];
    __shared__ __align__(16) __nv_bfloat16 sAl[128][ASTR];
    __shared__ __align__(16) __nv_bfloat16 sBh[64][ASTR];
    __shared__ __align__(16) __nv_bfloat16 sBl[64][ASTR];

    int bm = blockIdx.x * 128;
    int by = blockIdx.y;
    int mat = by >> 2;

    int tid  = threadIdx.x;
    int wid  = tid >> 5;
    int lane = tid & 31;
    int wm = wid & 3;
    int wn = wid >> 2;
    int g = lane >> 2, t = lane & 3;

    float acc[2][4][4];
#pragma unroll
    for (int a = 0; a < 2; a++)
#pragma unroll
        for (int b = 0; b < 4; b++)
#pragma unroll
            for (int c = 0; c < 4; c++) acc[a][b][c] = 0.f;

    for (int stage = 0; stage < 8; stage++) {
        int k0 = stage * 32;
        for (int idx = tid; idx < 128 * 8; idx += 256) {
            int row = idx >> 3, c4 = (idx & 7) * 4;
            int m = bm + row;
            uint2 vh = make_uint2(0u, 0u), vl = make_uint2(0u, 0u);
            if (m < NN) {
                vh = *(const uint2*)&g_xh[m * 256 + k0 + c4];
                vl = *(const uint2*)&g_xl[m * 256 + k0 + c4];
            }
            *(uint2*)&sAh[row][c4] = vh;
            *(uint2*)&sAl[row][c4] = vl;
        }
        for (int idx = tid; idx < 64 * 8; idx += 256) {
            int row = idx >> 3, c4 = (idx & 7) * 4;
            int np = by * 64 + row;
            *(uint2*)&sBh[row][c4] = *(const uint2*)&g_wh[np * 256 + k0 + c4];
            *(uint2*)&sBl[row][c4] = *(const uint2*)&g_wl[np * 256 + k0 + c4];
        }
        __syncthreads();

#pragma unroll
        for (int ks = 0; ks < 32; ks += 16) {
            uint32_t ah[2][4], al[2][4], bh[4][2], bl[4][2];
#pragma unroll
            for (int mt = 0; mt < 2; mt++) {
                int r0 = wm * 32 + mt * 16 + g;
                ah[mt][0] = *(const uint32_t*)&sAh[r0][ks + t * 2];
                ah[mt][1] = *(const uint32_t*)&sAh[r0 + 8][ks + t * 2];
                ah[mt][2] = *(const uint32_t*)&sAh[r0][ks + t * 2 + 8];
                ah[mt][3] = *(const uint32_t*)&sAh[r0 + 8][ks + t * 2 + 8];
                al[mt][0] = *(const uint32_t*)&sAl[r0][ks + t * 2];
                al[mt][1] = *(const uint32_t*)&sAl[r0 + 8][ks + t * 2];
                al[mt][2] = *(const uint32_t*)&sAl[r0][ks + t * 2 + 8];
                al[mt][3] = *(const uint32_t*)&sAl[r0 + 8][ks + t * 2 + 8];
            }
#pragma unroll
            for (int nt = 0; nt < 4; nt++) {
                int r0 = wn * 32 + nt * 8 + g;
                bh[nt][0] = *(const uint32_t*)&sBh[r0][ks + t * 2];
                bh[nt][1] = *(const uint32_t*)&sBh[r0][ks + t * 2 + 8];
                bl[nt][0] = *(const uint32_t*)&sBl[r0][ks + t * 2];
                bl[nt][1] = *(const uint32_t*)&sBl[r0][ks + t * 2 + 8];
            }
#pragma unroll
            for (int mt = 0; mt < 2; mt++)
#pragma unroll
                for (int nt = 0; nt < 4; nt++) {
                    mma16816(acc[mt][nt], ah[mt], bh[nt]);
                    mma16816(acc[mt][nt], ah[mt], bl[nt]);
                    mma16816(acc[mt][nt], al[mt], bh[nt]);
                }
        }
        __syncthreads();
    }

    const float* bias = (mat == 0) ? bk : ((mat == 1) ? bq : bv);
    float*       outp = (mat == 0) ? g_k : ((mat == 1) ? g_q : g_v);
    int nbase = (by & 3) * 64 + wn * 32;

#pragma unroll
    for (int mt = 0; mt < 2; mt++) {
        int m0 = bm + wm * 32 + mt * 16 + g;
#pragma unroll
        for (int nt = 0; nt < 4; nt++) {
            int col = nbase + nt * 8 + t * 2;
            float2 bb = *(const float2*)&bias[col];
            if (m0 < NN) {
                float ox = acc[mt][nt][0] + bb.x, oy = acc[mt][nt][1] + bb.y;
                *(float2*)&outp[m0 * 256 + col] = make_float2(ox, oy);
                if (mat == 1) {
                    *(uint32_t*)&g_qh[m0 * 256 + col] = pack_hi2(ox, oy);
                    *(uint32_t*)&g_ql[m0 * 256 + col] = pack_lo2(ox, oy);
                }
            }
            if (m0 + 8 < NN) {
                float ox = acc[mt][nt][2] + bb.x, oy = acc[mt][nt][3] + bb.y;
                *(float2*)&outp[(m0 + 8) * 256 + col] = make_float2(ox, oy);
                if (mat == 1) {
                    *(uint32_t*)&g_qh[(m0 + 8) * 256 + col] = pack_hi2(ox, oy);
                    *(uint32_t*)&g_ql[(m0 + 8) * 256 + col] = pack_lo2(ox, oy);
                }
            }
        }
    }
}

// ---------------- K2: qcf = q @ CF[ct]^T for all 3 ct variants ------------------
__global__ __launch_bounds__(256) void k_q3_tc()
{
    __shared__ __align__(16) __nv_bfloat16 sQh[128][ASTR];
    __shared__ __align__(16) __nv_bfloat16 sQl[128][ASTR];

    int base = blockIdx.x * 128;
    int h    = blockIdx.y;
    int tid  = threadIdx.x;
    int wid  = tid >> 5;
    int lane = tid & 31;
    int g = lane >> 2, t = lane & 3;

    for (int idx = tid; idx < 128 * 8; idx += 256) {
        int row = idx >> 3, c4 = (idx & 7) * 4;
        int m = base + row;
        uint2 qh = make_uint2(0u, 0u), ql = qh;
        if (m < NN) {
            int o = m * 256 + h * 32 + c4;
            qh = *(const uint2*)&g_qh[o];
            ql = *(const uint2*)&g_ql[o];
        }
        *(uint2*)&sQh[row][c4] = qh;
        *(uint2*)&sQl[row][c4] = ql;
    }
    __syncthreads();

    int r0 = wid * 16 + g;
    uint32_t qAh[2][4], qAl[2][4];
#pragma unroll
    for (int ki = 0; ki < 2; ki++) {
        int ks = ki * 16;
        qAh[ki][0] = *(const uint32_t*)&sQh[r0][ks + t * 2];
        qAh[ki][1] = *(const uint32_t*)&sQh[r0 + 8][ks + t * 2];
        qAh[ki][2] = *(const uint32_t*)&sQh[r0][ks + t * 2 + 8];
        qAh[ki][3] = *(const uint32_t*)&sQh[r0 + 8][ks + t * 2 + 8];
        qAl[ki][0] = *(const uint32_t*)&sQl[r0][ks + t * 2];
        qAl[ki][1] = *(const uint32_t*)&sQl[r0 + 8][ks + t * 2];
        qAl[ki][2] = *(const uint32_t*)&sQl[r0][ks + t * 2 + 8];
        qAl[ki][3] = *(const uint32_t*)&sQl[r0 + 8][ks + t * 2 + 8];
    }

    int row0 = base + r0;
    int row1 = row0 + 8;
    const __nv_bfloat16* cbh = &g_cfbh[h * 96 * 32];
    const __nv_bfloat16* cbl = &g_cfbl[h * 96 * 32];

#pragma unroll
    for (int ct = 0; ct < 3; ct++) {
#pragma unroll
        for (int nt = 0; nt < 4; nt++) {
            int np = ct * 32 + nt * 8;
            float acc[4] = {0.f, 0.f, 0.f, 0.f};
#pragma unroll
            for (int ki = 0; ki < 2; ki++) {
                int ks = ki * 16;
                uint32_t bh[2], bl[2];
                bh[0] = *(const uint32_t*)&cbh[(np + g) * 32 + ks + t * 2];
                bh[1] = *(const uint32_t*)&cbh[(np + g) * 32 + ks + t * 2 + 8];
                bl[0] = *(const uint32_t*)&cbl[(np + g) * 32 + ks + t * 2];
                bl[1] = *(const uint32_t*)&cbl[(np + g) * 32 + ks + t * 2 + 8];
                mma16816(acc, qAh[ki], bh);
                mma16816(acc, qAh[ki], bl);
                mma16816(acc, qAl[ki], bh);
            }
            int ei = nt * 8 + t * 2;
            if (row0 < NN)
                *(float2*)&g_qcf[(row0 * 3 + ct) * 256 + h * 32 + ei] =
                    make_float2(acc[0], acc[1]);
            if (row1 < NN)
                *(float2*)&g_qcf[(row1 * 3 + ct) * 256 + h * 32 + ei] =
                    make_float2(acc[2], acc[3]);
        }
    }
}

// ---------------- K3: CSR build ------------------------------------------------
__global__ void k_zero()
{
    int i = blockIdx.x * 256 + threadIdx.x;
    if (i < 3 * NN) {
        ((int*)g_cnt)[i] = 0;
        ((int*)g_cur)[i] = 0;
    }
}

__global__ void k_count(const int* __restrict__ dst)
{
    int i = blockIdx.x * 256 + threadIdx.x;
    if (i < 3 * EE) {
        int e = i / EE;
        atomicAdd(&g_cnt[e][dst[i]], 1);
    }
}

__global__ __launch_bounds__(1024) void k_scan()
{
    __shared__ int s[1024];
    int t = threadIdx.x;
    for (int e = 0; e < 3; e++) {
        int carry = 0;
        if (t == 0) g_off[e][0] = 0;
        for (int base = 0; base < NN; base += 1024) {
            int v = (base + t < NN) ? g_cnt[e][base + t] : 0;
            s[t] = v;
            __syncthreads();
            for (int ofs = 1; ofs < 1024; ofs <<= 1) {
                int add = (t >= ofs) ? s[t - ofs] : 0;
                __syncthreads();
                s[t] += add;
                __syncthreads();
            }
            if (base + t < NN) g_off[e][base + t + 1] = carry + s[t];
            carry += s[1023];
            __syncthreads();
        }
    }
}

__global__ void k_scatter(const int* __restrict__ src, const int* __restrict__ dst)
{
    int i = blockIdx.x * 256 + threadIdx.x;
    if (i < 3 * EE) {
        int e = i / EE;
        int d = dst[i];
        int pos = g_off[e][d] + atomicAdd(&g_cur[e][d], 1);
        g_ssrc[e][pos] = src[i];
        g_sdst[e][pos] = d;
    }
}

// ---------------- K4: edge logits (warp per edge; only k[s] random) -------------
__global__ __launch_bounds__(256) void k_att(const float* __restrict__ pri,
                                             const float* __restrict__ pri_cau,
                                             const int* __restrict__ cau_type)
{
    int e = blockIdx.y;
    int w = blockIdx.x * 8 + (threadIdx.x >> 5);
    int l = threadIdx.x & 31;
    if (w >= EE) return;

    int s = g_ssrc[e][w];
    int d = g_sdst[e][w];
    int ct = cau_type[s];

    const float* qp = &g_q[d * 256 + l * 8];
    const float* kp = &g_k[s * 256 + l * 8];
    const float* cp = &g_qcf[(d * 3 + ct) * 256 + l * 8];

    float4 q0 = *(const float4*)qp, q1 = *(const float4*)(qp + 4);
    float4 k0 = *(const float4*)kp, k1 = *(const float4*)(kp + 4);
    float4 c0 = *(const float4*)cp, c1 = *(const float4*)(cp + 4);

    float pa = q0.x * k0.x + q0.y * k0.y + q0.z * k0.z + q0.w * k0.w
             + q1.x * k1.x + q1.y * k1.y + q1.z * k1.z + q1.w * k1.w;
    float pc = c0.x * k0.x + c0.y * k0.y + c0.z * k0.z + c0.w * k0.w
             + c1.x * k1.x + c1.y * k1.y + c1.z * k1.z + c1.w * k1.w;

    pa += __shfl_xor_sync(0xffffffffu, pa, 1);
    pa += __shfl_xor_sync(0xffffffffu, pa, 2);
    pc += __shfl_xor_sync(0xffffffffu, pc, 1);
    pc += __shfl_xor_sync(0xffffffffu, pc, 2);

    const float inv_sqrt = 0.17677669529663687f;  // 1/sqrt(32)
    float av = __shfl_sync(0xffffffffu, pa, (l & 7) * 4);
    float cv = __shfl_sync(0xffffffffu, pc, (l & 7) * 4);

    if (l < 8) {
        g_attb[e][w * 8 + l] = av * pri[e * 8 + l] * inv_sqrt;
    } else if (l < 16) {
        int h = l - 8;
        g_cattb[e][w * 8 + h] = cv * pri_cau[e * 8 + h] * inv_sqrt;
    }
}

// ---------------- K5: segment softmax ------------------------------------------
__global__ void k_soft()
{
    int i = blockIdx.x * 256 + threadIdx.x;
    if (i >= 3 * NN * HH) return;
    int e = i / (NN * HH);
    int rem = i - e * (NN * HH);
    int d = rem >> 3;
    int h = rem & 7;

    int st = g_off[e][d], en = g_off[e][d + 1];
    float m = -1e30f, m2 = -1e30f;
    for (int p = st; p < en; p++) {
        m  = fmaxf(m,  g_attb[e][p * 8 + h]);
        m2 = fmaxf(m2, g_cattb[e][p * 8 + h]);
    }
    float s = 0.f, s2 = 0.f;
    for (int p = st; p < en; p++) {
        float w  = __expf(g_attb[e][p * 8 + h] - m);
        float w2 = __expf(g_cattb[e][p * 8 + h] - m2);
        g_attb[e][p * 8 + h] = w;
        g_cattb[e][p * 8 + h] = w2;
        s += w; s2 += w2;
    }
    g_inva[e][d * 8 + h] = (en > st) ? 1.0f / s  : 0.0f;
    g_invc[e][d * 8 + h] = (en > st) ? 1.0f / s2 : 0.0f;
}

// ---------------- K6: aggregation -> S1/S2 (gathers raw v only) -----------------
__global__ __launch_bounds__(256) void k_agg_s()
{
    int d = blockIdx.x * 8 + (threadIdx.x >> 5);
    int l = threadIdx.x & 31;
    if (d >= NN) return;

    for (int e = 0; e < 3; e++) {
        int st = g_off[e][d], en = g_off[e][d + 1];
        float inv = 0.f;
        if (l < 8)        inv = g_inva[e][d * 8 + l];
        else if (l < 16)  inv = g_invc[e][d * 8 + (l - 8)];

        float aH[8], aC[8];
#pragma unroll
        for (int r = 0; r < 8; r++) { aH[r] = 0.f; aC[r] = 0.f; }

        for (int p = st; p < en; p++) {
            int s = g_ssrc[e][p];
            float wl = 0.f;
            if (l < 8)        wl = g_attb[e][p * 8 + l];
            else if (l < 16)  wl = g_cattb[e][p * 8 + (l - 8)];
            wl *= inv;

            const float* vp = &g_v[s * 256 + l];
#pragma unroll
            for (int r = 0; r < 8; r++) {
                float wr = __shfl_sync(0xffffffffu, wl, r);
                float cr = __shfl_sync(0xffffffffu, wl, r + 8);
                float vv = vp[r * 32];
                aH[r] = fmaf(wr, vv, aH[r]);
                aC[r] = fmaf(cr, vv, aC[r]);
            }
        }
#pragma unroll
        for (int r = 0; r < 8; r++) {
            g_sc[(d * 8 + r) * 192 + e * 32 + l]      = aH[r];
            g_sc[(d * 8 + r) * 192 + 96 + e * 32 + l] = aC[r];
        }
    }
}

// ---------------- K7: post GEMM: out = relu(mean_e(S1@MSG + S2@MSGC' + bias)) ---
__global__ __launch_bounds__(256) void k_post_tc(float* __restrict__ out)
{
    __shared__ __align__(16) __nv_bfloat16 sAh[128][ASTR];
    __shared__ __align__(16) __nv_bfloat16 sAl[128][ASTR];

    int base = blockIdx.x * 128;
    int h    = blockIdx.y;
    int tid  = threadIdx.x;
    int wid  = tid >> 5;
    int lane = tid & 31;
    int g = lane >> 2, t = lane & 3;

    float acc[4][4];
#pragma unroll
    for (int a = 0; a < 4; a++)
#pragma unroll
        for (int c = 0; c < 4; c++) acc[a][c] = 0.f;

    const __nv_bfloat16* pbh = &g_pbh[h * 32 * 192];
    const __nv_bfloat16* pbl = &g_pbl[h * 32 * 192];

    for (int stage = 0; stage < 6; stage++) {
        int k0 = stage * 32;
        for (int idx = tid; idx < 128 * 8; idx += 256) {
            int row = idx >> 3, c4 = (idx & 7) * 4;
            int m = base + row;
            float4 v = make_float4(0.f, 0.f, 0.f, 0.f);
            if (m < NN) v = *(const float4*)&g_sc[(m * 8 + h) * 192 + k0 + c4];
            sAh[row][c4 + 0] = __float2bfloat16(v.x);
            sAh[row][c4 + 1] = __float2bfloat16(v.y);
            sAh[row][c4 + 2] = __float2bfloat16(v.z);
            sAh[row][c4 + 3] = __float2bfloat16(v.w);
            sAl[row][c4 + 0] = __float2bfloat16(v.x - __bfloat162float(sAh[row][c4 + 0]));
            sAl[row][c4 + 1] = __float2bfloat16(v.y - __bfloat162float(sAh[row][c4 + 1]));
            sAl[row][c4 + 2] = __float2bfloat16(v.z - __bfloat162float(sAh[row][c4 + 2]));
            sAl[row][c4 + 3] = __float2bfloat16(v.w - __bfloat162float(sAh[row][c4 + 3]));
        }
        __syncthreads();

        int r0 = wid * 16 + g;
#pragma unroll
        for (int ki = 0; ki < 2; ki++) {
            int ks = ki * 16;
            uint32_t ah[4], al[4];
            ah[0] = *(const uint32_t*)&sAh[r0][ks + t * 2];
            ah[1] = *(const uint32_t*)&sAh[r0 + 8][ks + t * 2];
            ah[2] = *(const uint32_t*)&sAh[r0][ks + t * 2 + 8];
            ah[3] = *(const uint32_t*)&sAh[r0 + 8][ks + t * 2 + 8];
            al[0] = *(const uint32_t*)&sAl[r0][ks + t * 2];
            al[1] = *(const uint32_t*)&sAl[r0 + 8][ks + t * 2];
            al[2] = *(const uint32_t*)&sAl[r0][ks + t * 2 + 8];
            al[3] = *(const uint32_t*)&sAl[r0 + 8][ks + t * 2 + 8];
#pragma unroll
            for (int nt = 0; nt < 4; nt++) {
                int n = nt * 8 + g;
                uint32_t bh[2], bl[2];
                bh[0] = *(const uint32_t*)&pbh[n * 192 + k0 + ks + t * 2];
                bh[1] = *(const uint32_t*)&pbh[n * 192 + k0 + ks + t * 2 + 8];
                bl[0] = *(const uint32_t*)&pbl[n * 192 + k0 + ks + t * 2];
                bl[1] = *(const uint32_t*)&pbl[n * 192 + k0 + ks + t * 2 + 8];
                mma16816(acc[nt], ah, bh);
                mma16816(acc[nt], ah, bl);
                mma16816(acc[nt], al, bh);
            }
        }
        __syncthreads();
    }

    int r0 = wid * 16 + g;
    int row0 = base + r0, row1 = row0 + 8;
    float ne0[3], ne1[3];
#pragma unroll
    for (int e = 0; e < 3; e++) {
        ne0[e] = (row0 < NN && g_off[e][row0 + 1] > g_off[e][row0]) ? 1.f : 0.f;
        ne1[e] = (row1 < NN && g_off[e][row1 + 1] > g_off[e][row1]) ? 1.f : 0.f;
    }
#pragma unroll
    for (int nt = 0; nt < 4; nt++) {
        int f = nt * 8 + t * 2;
        float b0x = 0.f, b0y = 0.f, b1x = 0.f, b1y = 0.f;
#pragma unroll
        for (int e = 0; e < 3; e++) {
            float2 bb = *(const float2*)&g_bias2[(e * 8 + h) * 32 + f];
            b0x += ne0[e] * bb.x; b0y += ne0[e] * bb.y;
            b1x += ne1[e] * bb.x; b1y += ne1[e] * bb.y;
        }
        const float third = 1.0f / 3.0f;
        if (row0 < NN)
            *(float2*)&out[row0 * 256 + h * 32 + f] = make_float2(
                fmaxf((acc[nt][0] + b0x) * third, 0.f),
                fmaxf((acc[nt][1] + b0y) * third, 0.f));
        if (row1 < NN)
            *(float2*)&out[row1 * 256 + h * 32 + f] = make_float2(
                fmaxf((acc[nt][2] + b1x) * third, 0.f),
                fmaxf((acc[nt][3] + b1y) * third, 0.f));
    }
}

// ---------------- launch -------------------------------------------------------
extern "C" void kernel_launch(void* const* d_in, const int* in_sizes, int n_in,
                              void* d_out, int out_size)
{
    const float* x          = (const float*)d_in[0];
    const float* Wk         = (const float*)d_in[1];
    const float* bk         = (const float*)d_in[2];
    const float* Wq         = (const float*)d_in[3];
    const float* bq         = (const float*)d_in[4];
    const float* Wv         = (const float*)d_in[5];
    const float* bv         = (const float*)d_in[6];
    const float* pri        = (const float*)d_in[7];
    const float* msg        = (const float*)d_in[8];
    const float* pri_cau    = (const float*)d_in[9];
    const float* msg_cau    = (const float*)d_in[10];
    const float* comb_pri   = (const float*)d_in[11];
    const float* cau_filter = (const float*)d_in[12];
    const float* time_emb   = (const float*)d_in[13];
    const int*   cau_type   = (const int*)d_in[14];
    const int*   src        = (const int*)d_in[15];
    const int*   dst        = (const int*)d_in[16];
    float* out = (float*)d_out;

    k_cvt_x<<<(NN * DD + 255) / 256, 256>>>(x);
    k_cvt_w<<<(3 * 256 * 256 + 255) / 256, 256>>>(Wk, Wq, Wv);
    k_prep<<<(CFB_N + PB_N + 3 * HH * 32 + 255) / 256, 256>>>(msg, msg_cau,
                                                              cau_filter, time_emb,
                                                              comb_pri);
    k_gemm_tc<<<dim3((NN + 127) / 128, 12), 256>>>(bk, bq, bv);
    k_q3_tc<<<dim3((NN + 127) / 128, HH), 256>>>();
    k_zero<<<(3 * NN + 255) / 256, 256>>>();
    k_count<<<(3 * EE + 255) / 256, 256>>>(dst);
    k_scan<<<1, 1024>>>();
    k_scatter<<<(3 * EE + 255) / 256, 256>>>(src, dst);
    k_att<<<dim3(EE / 8, 3), 256>>>(pri, pri_cau, cau_type);
    k_soft<<<(3 * NN * HH + 255) / 256, 256>>>();
    k_agg_s<<<(NN + 7) / 8, 256>>>();
    k_post_tc<<<dim3((NN + 127) / 128, HH), 256>>>(out);
}